// round 1
// baseline (speedup 1.0000x reference)
#include <cuda_runtime.h>
#include <math.h>

#define BATCH 16
#define SEQ   2048
#define DH    64
#define BM    64
#define BN    64
#define PAD   68          // floats per smem row: 68*4B stride -> conflict-free LDS.128
#define NTHR  256
#define SMEM_BYTES (4u * BM * PAD * sizeof(float))   // q,k,v,p tiles = 69632 B

__global__ __launch_bounds__(NTHR)
void flash_attn_fp32(const float* __restrict__ Q, const float* __restrict__ K,
                     const float* __restrict__ V, float* __restrict__ O)
{
    extern __shared__ float smem[];
    float* q_s = smem;
    float* k_s = q_s + BM * PAD;
    float* v_s = k_s + BN * PAD;
    float* p_s = v_s + BN * PAD;

    const int tid = threadIdx.x;
    const int iq  = blockIdx.x;           // query tile index
    const int b   = blockIdx.y;           // batch
    const int q0  = iq * BM;

    const int rg   = tid >> 4;            // 16 row-groups of 4 rows
    const int cg   = tid & 15;            // 16 col/dim-groups of 4
    const int row0 = rg << 2;
    const int col0 = cg << 2;

    const float* Qb = Q + (size_t)b * SEQ * DH;
    const float* Kb = K + (size_t)b * SEQ * DH;
    const float* Vb = V + (size_t)b * SEQ * DH;
    float*       Ob = O + (size_t)b * SEQ * DH;

    // ---- load Q tile once (coalesced float4) ----
    for (int idx = tid; idx < BM * (DH / 4); idx += NTHR) {
        int r  = idx >> 4;
        int d4 = (idx & 15) << 2;
        *(float4*)&q_s[r * PAD + d4] = *(const float4*)&Qb[(size_t)(q0 + r) * DH + d4];
    }

    float m[4], l[4], acc[4][4];
    #pragma unroll
    for (int r = 0; r < 4; r++) {
        m[r] = -1e30f; l[r] = 0.f;
        #pragma unroll
        for (int d = 0; d < 4; d++) acc[r][d] = 0.f;
    }

    for (int j = 0; j <= iq; ++j) {
        const int k0 = j * BN;

        __syncthreads();   // prev-iter PV reads of v_s/p_s done before overwrite
        for (int idx = tid; idx < BN * (DH / 4); idx += NTHR) {
            int r  = idx >> 4;
            int d4 = (idx & 15) << 2;
            *(float4*)&k_s[r * PAD + d4] = *(const float4*)&Kb[(size_t)(k0 + r) * DH + d4];
            *(float4*)&v_s[r * PAD + d4] = *(const float4*)&Vb[(size_t)(k0 + r) * DH + d4];
        }
        __syncthreads();   // tiles ready

        // ---- S = (Q K^T) * scale, 4x4 per thread ----
        float s[4][4];
        #pragma unroll
        for (int r = 0; r < 4; r++)
            #pragma unroll
            for (int c = 0; c < 4; c++) s[r][c] = 0.f;

        #pragma unroll
        for (int kk = 0; kk < DH; kk += 4) {
            float4 qf4[4], kf4[4];
            #pragma unroll
            for (int r = 0; r < 4; r++)
                qf4[r] = *(const float4*)&q_s[(row0 + r) * PAD + kk];
            #pragma unroll
            for (int c = 0; c < 4; c++)
                kf4[c] = *(const float4*)&k_s[(col0 + c) * PAD + kk];
            #pragma unroll
            for (int r = 0; r < 4; r++) {
                const float* qf = (const float*)&qf4[r];
                #pragma unroll
                for (int c = 0; c < 4; c++) {
                    const float* kf = (const float*)&kf4[c];
                    #pragma unroll
                    for (int t = 0; t < 4; t++)
                        s[r][c] = fmaf(qf[t], kf[t], s[r][c]);
                }
            }
        }

        // scale + causal mask (only the diagonal tile can have masked entries;
        // expf(-1e30 - m) == 0, numerically identical to reference's (s-1e6) path)
        const bool diag = (j == iq);
        #pragma unroll
        for (int r = 0; r < 4; r++)
            #pragma unroll
            for (int c = 0; c < 4; c++) {
                float sv = s[r][c] * 0.125f;
                if (diag && (col0 + c) > (row0 + r)) sv = -1e30f;
                s[r][c] = sv;
            }

        // ---- online softmax (row reductions across the 16-lane col group) ----
        float alpha[4];
        #pragma unroll
        for (int r = 0; r < 4; r++) {
            float tm = fmaxf(fmaxf(s[r][0], s[r][1]), fmaxf(s[r][2], s[r][3]));
            #pragma unroll
            for (int o = 8; o; o >>= 1)
                tm = fmaxf(tm, __shfl_xor_sync(0xffffffffu, tm, o));
            float nm = fmaxf(m[r], tm);
            float p0 = __expf(s[r][0] - nm);
            float p1 = __expf(s[r][1] - nm);
            float p2 = __expf(s[r][2] - nm);
            float p3 = __expf(s[r][3] - nm);
            float ps = (p0 + p1) + (p2 + p3);
            #pragma unroll
            for (int o = 8; o; o >>= 1)
                ps += __shfl_xor_sync(0xffffffffu, ps, o);
            float al = __expf(m[r] - nm);
            l[r] = l[r] * al + ps;
            m[r] = nm;
            alpha[r] = al;
            *(float4*)&p_s[(row0 + r) * PAD + col0] = make_float4(p0, p1, p2, p3);
        }
        __syncthreads();   // p_s ready for all threads

        // rescale running output
        #pragma unroll
        for (int r = 0; r < 4; r++)
            #pragma unroll
            for (int d = 0; d < 4; d++) acc[r][d] *= alpha[r];

        // ---- O += P * V, 4x4 per thread (dims = col0..col0+3) ----
        #pragma unroll
        for (int c = 0; c < BN; c += 4) {
            float vfr[4][4];
            #pragma unroll
            for (int cc = 0; cc < 4; cc++) {
                float4 t = *(const float4*)&v_s[(c + cc) * PAD + col0];
                vfr[cc][0] = t.x; vfr[cc][1] = t.y; vfr[cc][2] = t.z; vfr[cc][3] = t.w;
            }
            #pragma unroll
            for (int r = 0; r < 4; r++) {
                float4 t  = *(const float4*)&p_s[(row0 + r) * PAD + c];
                float pr[4] = {t.x, t.y, t.z, t.w};
                #pragma unroll
                for (int d = 0; d < 4; d++) {
                    float a = acc[r][d];
                    a = fmaf(pr[0], vfr[0][d], a);
                    a = fmaf(pr[1], vfr[1][d], a);
                    a = fmaf(pr[2], vfr[2][d], a);
                    a = fmaf(pr[3], vfr[3][d], a);
                    acc[r][d] = a;
                }
            }
        }
    }

    // ---- epilogue: normalize and store ----
    #pragma unroll
    for (int r = 0; r < 4; r++) {
        float inv = 1.0f / l[r];
        float4 o4 = make_float4(acc[r][0] * inv, acc[r][1] * inv,
                                acc[r][2] * inv, acc[r][3] * inv);
        *(float4*)&Ob[(size_t)(q0 + row0 + r) * DH + col0] = o4;
    }
}

extern "C" void kernel_launch(void* const* d_in, const int* in_sizes, int n_in,
                              void* d_out, int out_size)
{
    const float* q = (const float*)d_in[0];
    const float* k = (const float*)d_in[1];
    const float* v = (const float*)d_in[2];
    float*       o = (float*)d_out;

    cudaFuncSetAttribute(flash_attn_fp32,
                         cudaFuncAttributeMaxDynamicSharedMemorySize,
                         (int)SMEM_BYTES);

    dim3 grid(SEQ / BM, BATCH);
    flash_attn_fp32<<<grid, NTHR, SMEM_BYTES>>>(q, k, v, o);
}

// round 2
// speedup vs baseline: 5.1170x; 5.1170x over previous
#include <cuda_runtime.h>
#include <math.h>

#define BATCH 16
#define SEQ   2048
#define DH    64
#define BM    64
#define BN    64
#define PK    68        // k_s row pitch (floats): frag banks 4g+tg -> conflict-free
#define PVV   72        // v_s row pitch: frag banks 8tg+g -> conflict-free
#define PP    68        // p_s/q staging pitch
#define NTHR  128
#define SMEM_FLOATS (BN*PK + BN*PVV + BM*PP)
#define SMEM_BYTES  (SMEM_FLOATS * sizeof(float))   // 53248 B

__device__ __forceinline__ unsigned tf32r(float x) {
    unsigned u; asm("cvt.rna.tf32.f32 %0, %1;" : "=r"(u) : "f"(x)); return u;
}
__device__ __forceinline__ float tf32f(float x) { return __uint_as_float(tf32r(x)); }

__device__ __forceinline__ void mma_tf32(float& c0, float& c1, float& c2, float& c3,
                                         unsigned a0, unsigned a1, unsigned a2, unsigned a3,
                                         unsigned b0, unsigned b1) {
    asm volatile("mma.sync.aligned.m16n8k8.row.col.f32.tf32.tf32.f32 "
                 "{%0,%1,%2,%3}, {%4,%5,%6,%7}, {%8,%9}, {%0,%1,%2,%3};"
                 : "+f"(c0), "+f"(c1), "+f"(c2), "+f"(c3)
                 : "r"(a0), "r"(a1), "r"(a2), "r"(a3), "r"(b0), "r"(b1));
}

__global__ __launch_bounds__(NTHR)
void flash_attn_tf32(const float* __restrict__ Q, const float* __restrict__ K,
                     const float* __restrict__ V, float* __restrict__ O)
{
    extern __shared__ float smem[];
    float* k_s = smem;                 // [BN][PK]
    float* v_s = k_s + BN * PK;        // [BN][PVV]
    float* p_s = v_s + BN * PVV;       // [BM][PP] (also Q staging)

    const int tid  = threadIdx.x;
    const int w    = tid >> 5;         // warp 0..3, owns rows 16w..16w+15
    const int lane = tid & 31;
    const int g    = lane >> 2;        // group id 0..7
    const int tg   = lane & 3;         // thread-in-group 0..3

    const int iq = blockIdx.x;
    const int b  = blockIdx.y;
    const int q0 = iq * BM;

    const float* Qb = Q + (size_t)b * SEQ * DH;
    const float* Kb = K + (size_t)b * SEQ * DH;
    const float* Vb = V + (size_t)b * SEQ * DH;
    float*       Ob = O + (size_t)b * SEQ * DH;

    // ---- stage Q (tf32-rounded) into p_s, then read register fragments ----
    for (int idx = tid; idx < BM * (DH / 4); idx += NTHR) {
        int r  = idx >> 4;
        int d4 = (idx & 15) << 2;
        float4 t = *(const float4*)&Qb[(size_t)(q0 + r) * DH + d4];
        p_s[r * PP + d4 + 0] = tf32f(t.x);
        p_s[r * PP + d4 + 1] = tf32f(t.y);
        p_s[r * PP + d4 + 2] = tf32f(t.z);
        p_s[r * PP + d4 + 3] = tf32f(t.w);
    }
    __syncthreads();

    const int r0 = w * 16 + g;          // local row for frag slot 0/1; r0+8 for 2/3
    unsigned qf[8][4];
    #pragma unroll
    for (int kc = 0; kc < 8; kc++) {
        qf[kc][0] = __float_as_uint(p_s[(r0    ) * PP + kc * 8 + tg    ]);
        qf[kc][1] = __float_as_uint(p_s[(r0 + 8) * PP + kc * 8 + tg    ]);
        qf[kc][2] = __float_as_uint(p_s[(r0    ) * PP + kc * 8 + tg + 4]);
        qf[kc][3] = __float_as_uint(p_s[(r0 + 8) * PP + kc * 8 + tg + 4]);
    }

    float o[8][4];
    #pragma unroll
    for (int nc = 0; nc < 8; nc++)
        #pragma unroll
        for (int i = 0; i < 4; i++) o[nc][i] = 0.f;
    float m0 = -1e30f, m1 = -1e30f, l0 = 0.f, l1 = 0.f;

    const int growA = q0 + r0;          // global query row (slot 0/1); +8 for 2/3

    for (int j = 0; j <= iq; ++j) {
        const int k0 = j * BN;

        __syncthreads();   // previous iter's PV reads (and round-1 qf reads) done
        for (int idx = tid; idx < BN * (DH / 4); idx += NTHR) {
            int r  = idx >> 4;
            int d4 = (idx & 15) << 2;
            float4 kt = *(const float4*)&Kb[(size_t)(k0 + r) * DH + d4];
            float4 vt = *(const float4*)&Vb[(size_t)(k0 + r) * DH + d4];
            k_s[r * PK  + d4 + 0] = tf32f(kt.x);
            k_s[r * PK  + d4 + 1] = tf32f(kt.y);
            k_s[r * PK  + d4 + 2] = tf32f(kt.z);
            k_s[r * PK  + d4 + 3] = tf32f(kt.w);
            v_s[r * PVV + d4 + 0] = tf32f(vt.x);
            v_s[r * PVV + d4 + 1] = tf32f(vt.y);
            v_s[r * PVV + d4 + 2] = tf32f(vt.z);
            v_s[r * PVV + d4 + 3] = tf32f(vt.w);
        }
        __syncthreads();   // K,V tiles ready

        // ---- S = Q K^T (tf32 mma): warp computes 16x64 ----
        float s[8][4];
        #pragma unroll
        for (int nc = 0; nc < 8; nc++) {
            s[nc][0] = s[nc][1] = s[nc][2] = s[nc][3] = 0.f;
            #pragma unroll
            for (int kc = 0; kc < 8; kc++) {
                unsigned b0 = __float_as_uint(k_s[(nc * 8 + g) * PK + kc * 8 + tg    ]);
                unsigned b1 = __float_as_uint(k_s[(nc * 8 + g) * PK + kc * 8 + tg + 4]);
                mma_tf32(s[nc][0], s[nc][1], s[nc][2], s[nc][3],
                         qf[kc][0], qf[kc][1], qf[kc][2], qf[kc][3], b0, b1);
            }
        }

        // ---- scale + causal mask ----
        const bool diag = (j == iq);
        float mr0 = -1e30f, mr1 = -1e30f;
        #pragma unroll
        for (int nc = 0; nc < 8; nc++) {
            int c0col = k0 + nc * 8 + 2 * tg;
            #pragma unroll
            for (int i = 0; i < 4; i++) {
                float sv = s[nc][i] * 0.125f;
                if (diag) {
                    int col = c0col + (i & 1);
                    int row = growA + ((i >> 1) << 3);
                    if (col > row) sv = -1e30f;
                }
                s[nc][i] = sv;
            }
            mr0 = fmaxf(mr0, fmaxf(s[nc][0], s[nc][1]));
            mr1 = fmaxf(mr1, fmaxf(s[nc][2], s[nc][3]));
        }
        // row reduce across the 4 lanes sharing a row (lane bits 0-1)
        #pragma unroll
        for (int off = 1; off <= 2; off <<= 1) {
            mr0 = fmaxf(mr0, __shfl_xor_sync(0xffffffffu, mr0, off));
            mr1 = fmaxf(mr1, __shfl_xor_sync(0xffffffffu, mr1, off));
        }
        float nm0 = fmaxf(m0, mr0), nm1 = fmaxf(m1, mr1);

        float sum0 = 0.f, sum1 = 0.f;
        #pragma unroll
        for (int nc = 0; nc < 8; nc++) {
            float p0 = __expf(s[nc][0] - nm0);
            float p1 = __expf(s[nc][1] - nm0);
            float p2 = __expf(s[nc][2] - nm1);
            float p3 = __expf(s[nc][3] - nm1);
            sum0 += p0 + p1;  sum1 += p2 + p3;
            // write P (tf32-rounded) for the PV mma A-operand
            *(float2*)&p_s[(r0    ) * PP + nc * 8 + 2 * tg] = make_float2(tf32f(p0), tf32f(p1));
            *(float2*)&p_s[(r0 + 8) * PP + nc * 8 + 2 * tg] = make_float2(tf32f(p2), tf32f(p3));
        }
        #pragma unroll
        for (int off = 1; off <= 2; off <<= 1) {
            sum0 += __shfl_xor_sync(0xffffffffu, sum0, off);
            sum1 += __shfl_xor_sync(0xffffffffu, sum1, off);
        }
        float a0 = __expf(m0 - nm0), a1 = __expf(m1 - nm1);
        l0 = l0 * a0 + sum0;  l1 = l1 * a1 + sum1;
        m0 = nm0;             m1 = nm1;

        #pragma unroll
        for (int nc = 0; nc < 8; nc++) {
            o[nc][0] *= a0;  o[nc][1] *= a0;
            o[nc][2] *= a1;  o[nc][3] *= a1;
        }
        __syncthreads();   // p_s ready for all warps

        // ---- O += P V (tf32 mma): A = P[16x8 chunk], B = V[8x8] ----
        #pragma unroll
        for (int kc = 0; kc < 8; kc++) {
            unsigned pa0 = __float_as_uint(p_s[(r0    ) * PP + kc * 8 + tg    ]);
            unsigned pa1 = __float_as_uint(p_s[(r0 + 8) * PP + kc * 8 + tg    ]);
            unsigned pa2 = __float_as_uint(p_s[(r0    ) * PP + kc * 8 + tg + 4]);
            unsigned pa3 = __float_as_uint(p_s[(r0 + 8) * PP + kc * 8 + tg + 4]);
            #pragma unroll
            for (int nc = 0; nc < 8; nc++) {
                unsigned b0 = __float_as_uint(v_s[(kc * 8 + tg    ) * PVV + nc * 8 + g]);
                unsigned b1 = __float_as_uint(v_s[(kc * 8 + tg + 4) * PVV + nc * 8 + g]);
                mma_tf32(o[nc][0], o[nc][1], o[nc][2], o[nc][3],
                         pa0, pa1, pa2, pa3, b0, b1);
            }
        }
    }

    // ---- epilogue ----
    float inv0 = 1.0f / l0, inv1 = 1.0f / l1;
    #pragma unroll
    for (int nc = 0; nc < 8; nc++) {
        int col = nc * 8 + 2 * tg;
        *(float2*)&Ob[(size_t)(q0 + r0    ) * DH + col] =
            make_float2(o[nc][0] * inv0, o[nc][1] * inv0);
        *(float2*)&Ob[(size_t)(q0 + r0 + 8) * DH + col] =
            make_float2(o[nc][2] * inv1, o[nc][3] * inv1);
    }
}

extern "C" void kernel_launch(void* const* d_in, const int* in_sizes, int n_in,
                              void* d_out, int out_size)
{
    const float* q = (const float*)d_in[0];
    const float* k = (const float*)d_in[1];
    const float* v = (const float*)d_in[2];
    float*       o = (float*)d_out;

    cudaFuncSetAttribute(flash_attn_tf32,
                         cudaFuncAttributeMaxDynamicSharedMemorySize,
                         (int)SMEM_BYTES);

    dim3 grid(SEQ / BM, BATCH);
    flash_attn_tf32<<<grid, NTHR, SMEM_BYTES>>>(q, k, v, o);
}

// round 3
// speedup vs baseline: 5.3375x; 1.0431x over previous
#include <cuda_runtime.h>
#include <math.h>

#define BATCH 16
#define SEQ   2048
#define DH    64
#define BM    64
#define BN    64
#define PK    68
#define PVV   72
#define PP    68
#define NTHR  256
// per warpgroup: k(64*68) + v(64*72) + p(64*68) = 13312 floats
#define WG_FLOATS (BN*PK + BN*PVV + BM*PP)
#define SMEM_FLOATS (2 * WG_FLOATS)
#define SMEM_BYTES  (SMEM_FLOATS * sizeof(float))   // 106496 B

__device__ __forceinline__ unsigned tf32r(float x) {
    unsigned u; asm("cvt.rna.tf32.f32 %0, %1;" : "=r"(u) : "f"(x)); return u;
}
__device__ __forceinline__ float tf32f(float x) { return __uint_as_float(tf32r(x)); }

__device__ __forceinline__ void mma_tf32(float& c0, float& c1, float& c2, float& c3,
                                         unsigned a0, unsigned a1, unsigned a2, unsigned a3,
                                         unsigned b0, unsigned b1) {
    asm volatile("mma.sync.aligned.m16n8k8.row.col.f32.tf32.tf32.f32 "
                 "{%0,%1,%2,%3}, {%4,%5,%6,%7}, {%8,%9}, {%0,%1,%2,%3};"
                 : "+f"(c0), "+f"(c1), "+f"(c2), "+f"(c3)
                 : "r"(a0), "r"(a1), "r"(a2), "r"(a3), "r"(b0), "r"(b1));
}

__global__ __launch_bounds__(NTHR)
void flash_attn_tf32_wg(const float* __restrict__ Q, const float* __restrict__ K,
                        const float* __restrict__ V, float* __restrict__ O)
{
    extern __shared__ float smem[];

    const int tid  = threadIdx.x;
    const int wid  = tid >> 5;
    const int wg   = wid >> 2;          // warpgroup 0/1
    const int w4   = wid & 3;           // warp within group
    const int lane = tid & 31;
    const int g    = lane >> 2;
    const int tg   = lane & 3;

    float* k_s = smem + wg * WG_FLOATS;          // [BN][PK]
    float* v_s = k_s + BN * PK;                  // [BN][PVV]
    float* p_s = v_s + BN * PVV;                 // [BM][PP]
    float* q_stage = smem + (2 * WG_FLOATS - BM * PP);  // group1's p buffer for Q staging

    // heavy CTAs first: largest iq launches at blockIdx.x == 0
    const int iq = (gridDim.x - 1) - blockIdx.x;
    const int b  = blockIdx.y;
    const int q0 = iq * BM;

    const float* Qb = Q + (size_t)b * SEQ * DH;
    const float* Kb = K + (size_t)b * SEQ * DH;
    const float* Vb = V + (size_t)b * SEQ * DH;
    float*       Ob = O + (size_t)b * SEQ * DH;

    // ---- stage Q (tf32-rounded), all 256 threads ----
    for (int idx = tid; idx < BM * (DH / 4); idx += NTHR) {
        int r  = idx >> 4;
        int d4 = (idx & 15) << 2;
        float4 t = *(const float4*)&Qb[(size_t)(q0 + r) * DH + d4];
        q_stage[r * PP + d4 + 0] = tf32f(t.x);
        q_stage[r * PP + d4 + 1] = tf32f(t.y);
        q_stage[r * PP + d4 + 2] = tf32f(t.z);
        q_stage[r * PP + d4 + 3] = tf32f(t.w);
    }
    __syncthreads();

    const int r0 = w4 * 16 + g;          // local rows r0 / r0+8 (same for both groups)
    unsigned qf[8][4];
    #pragma unroll
    for (int kc = 0; kc < 8; kc++) {
        qf[kc][0] = __float_as_uint(q_stage[(r0    ) * PP + kc * 8 + tg    ]);
        qf[kc][1] = __float_as_uint(q_stage[(r0 + 8) * PP + kc * 8 + tg    ]);
        qf[kc][2] = __float_as_uint(q_stage[(r0    ) * PP + kc * 8 + tg + 4]);
        qf[kc][3] = __float_as_uint(q_stage[(r0 + 8) * PP + kc * 8 + tg + 4]);
    }
    __syncthreads();   // frags read before group-1's p buffer gets overwritten

    float o[8][4];
    #pragma unroll
    for (int nc = 0; nc < 8; nc++)
        #pragma unroll
        for (int i = 0; i < 4; i++) o[nc][i] = 0.f;
    float m0 = -1e30f, m1 = -1e30f, l0 = 0.f, l1 = 0.f;
    const int growA = q0 + r0;

    const int barid = 1 + wg;
    const int ltid  = tid & 127;        // thread id within warpgroup

    // group wg processes KV tiles j = wg, wg+2, ...
    for (int j = wg; j <= iq; j += 2) {
        const int k0 = j * BN;

        asm volatile("bar.sync %0, 128;" :: "r"(barid));   // prev PV reads done
        for (int idx = ltid; idx < BN * (DH / 4); idx += 128) {
            int r  = idx >> 4;
            int d4 = (idx & 15) << 2;
            float4 kt = *(const float4*)&Kb[(size_t)(k0 + r) * DH + d4];
            float4 vt = *(const float4*)&Vb[(size_t)(k0 + r) * DH + d4];
            k_s[r * PK  + d4 + 0] = tf32f(kt.x);
            k_s[r * PK  + d4 + 1] = tf32f(kt.y);
            k_s[r * PK  + d4 + 2] = tf32f(kt.z);
            k_s[r * PK  + d4 + 3] = tf32f(kt.w);
            v_s[r * PVV + d4 + 0] = tf32f(vt.x);
            v_s[r * PVV + d4 + 1] = tf32f(vt.y);
            v_s[r * PVV + d4 + 2] = tf32f(vt.z);
            v_s[r * PVV + d4 + 3] = tf32f(vt.w);
        }
        asm volatile("bar.sync %0, 128;" :: "r"(barid));   // tiles ready

        // ---- S = Q K^T ----
        float s[8][4];
        #pragma unroll
        for (int nc = 0; nc < 8; nc++) {
            s[nc][0] = s[nc][1] = s[nc][2] = s[nc][3] = 0.f;
            #pragma unroll
            for (int kc = 0; kc < 8; kc++) {
                unsigned b0 = __float_as_uint(k_s[(nc * 8 + g) * PK + kc * 8 + tg    ]);
                unsigned b1 = __float_as_uint(k_s[(nc * 8 + g) * PK + kc * 8 + tg + 4]);
                mma_tf32(s[nc][0], s[nc][1], s[nc][2], s[nc][3],
                         qf[kc][0], qf[kc][1], qf[kc][2], qf[kc][3], b0, b1);
            }
        }

        // ---- scale + causal mask ----
        const bool diag = (j == iq);
        float mr0 = -1e30f, mr1 = -1e30f;
        #pragma unroll
        for (int nc = 0; nc < 8; nc++) {
            int c0col = k0 + nc * 8 + 2 * tg;
            #pragma unroll
            for (int i = 0; i < 4; i++) {
                float sv = s[nc][i] * 0.125f;
                if (diag) {
                    int col = c0col + (i & 1);
                    int row = growA + ((i >> 1) << 3);
                    if (col > row) sv = -1e30f;
                }
                s[nc][i] = sv;
            }
            mr0 = fmaxf(mr0, fmaxf(s[nc][0], s[nc][1]));
            mr1 = fmaxf(mr1, fmaxf(s[nc][2], s[nc][3]));
        }
        #pragma unroll
        for (int off = 1; off <= 2; off <<= 1) {
            mr0 = fmaxf(mr0, __shfl_xor_sync(0xffffffffu, mr0, off));
            mr1 = fmaxf(mr1, __shfl_xor_sync(0xffffffffu, mr1, off));
        }
        float nm0 = fmaxf(m0, mr0), nm1 = fmaxf(m1, mr1);

        float sum0 = 0.f, sum1 = 0.f;
        #pragma unroll
        for (int nc = 0; nc < 8; nc++) {
            float p0 = __expf(s[nc][0] - nm0);
            float p1 = __expf(s[nc][1] - nm0);
            float p2 = __expf(s[nc][2] - nm1);
            float p3 = __expf(s[nc][3] - nm1);
            sum0 += p0 + p1;  sum1 += p2 + p3;
            *(float2*)&p_s[(r0    ) * PP + nc * 8 + 2 * tg] = make_float2(tf32f(p0), tf32f(p1));
            *(float2*)&p_s[(r0 + 8) * PP + nc * 8 + 2 * tg] = make_float2(tf32f(p2), tf32f(p3));
        }
        #pragma unroll
        for (int off = 1; off <= 2; off <<= 1) {
            sum0 += __shfl_xor_sync(0xffffffffu, sum0, off);
            sum1 += __shfl_xor_sync(0xffffffffu, sum1, off);
        }
        float a0 = __expf(m0 - nm0), a1 = __expf(m1 - nm1);
        l0 = l0 * a0 + sum0;  l1 = l1 * a1 + sum1;
        m0 = nm0;             m1 = nm1;

        #pragma unroll
        for (int nc = 0; nc < 8; nc++) {
            o[nc][0] *= a0;  o[nc][1] *= a0;
            o[nc][2] *= a1;  o[nc][3] *= a1;
        }
        asm volatile("bar.sync %0, 128;" :: "r"(barid));   // p_s ready

        // ---- O += P V ----
        #pragma unroll
        for (int kc = 0; kc < 8; kc++) {
            unsigned pa0 = __float_as_uint(p_s[(r0    ) * PP + kc * 8 + tg    ]);
            unsigned pa1 = __float_as_uint(p_s[(r0 + 8) * PP + kc * 8 + tg    ]);
            unsigned pa2 = __float_as_uint(p_s[(r0    ) * PP + kc * 8 + tg + 4]);
            unsigned pa3 = __float_as_uint(p_s[(r0 + 8) * PP + kc * 8 + tg + 4]);
            #pragma unroll
            for (int nc = 0; nc < 8; nc++) {
                unsigned b0 = __float_as_uint(v_s[(kc * 8 + tg    ) * PVV + nc * 8 + g]);
                unsigned b1 = __float_as_uint(v_s[(kc * 8 + tg + 4) * PVV + nc * 8 + g]);
                mma_tf32(o[nc][0], o[nc][1], o[nc][2], o[nc][3],
                         pa0, pa1, pa2, pa3, b0, b1);
            }
        }
    }

    // ---- merge the two warpgroups' partial results ----
    __syncthreads();    // both groups done; buffers reusable
    float* om = smem;                 // 64 x 68 merge area (group0 k buffer)
    float* st = smem + BN * PK;       // stats: m[64], l[64]

    if (wg == 1) {
        #pragma unroll
        for (int nc = 0; nc < 8; nc++) {
            int col = nc * 8 + 2 * tg;
            *(float2*)&om[(r0    ) * PP + col] = make_float2(o[nc][0], o[nc][1]);
            *(float2*)&om[(r0 + 8) * PP + col] = make_float2(o[nc][2], o[nc][3]);
        }
        if (tg == 0) {
            st[r0] = m0;       st[64 + r0] = l0;
            st[r0 + 8] = m1;   st[64 + r0 + 8] = l1;
        }
    }
    __syncthreads();

    if (wg == 0) {
        float mb0 = st[r0],     lb0 = st[64 + r0];
        float mb1 = st[r0 + 8], lb1 = st[64 + r0 + 8];
        float M0 = fmaxf(m0, mb0), M1 = fmaxf(m1, mb1);
        float ea0 = __expf(m0 - M0),  eb0 = __expf(mb0 - M0);
        float ea1 = __expf(m1 - M1),  eb1 = __expf(mb1 - M1);
        float inv0 = 1.0f / (l0 * ea0 + lb0 * eb0);
        float inv1 = 1.0f / (l1 * ea1 + lb1 * eb1);
        #pragma unroll
        for (int nc = 0; nc < 8; nc++) {
            int col = nc * 8 + 2 * tg;
            float2 tb0 = *(const float2*)&om[(r0    ) * PP + col];
            float2 tb1 = *(const float2*)&om[(r0 + 8) * PP + col];
            *(float2*)&Ob[(size_t)(q0 + r0    ) * DH + col] =
                make_float2((o[nc][0] * ea0 + tb0.x * eb0) * inv0,
                            (o[nc][1] * ea0 + tb0.y * eb0) * inv0);
            *(float2*)&Ob[(size_t)(q0 + r0 + 8) * DH + col] =
                make_float2((o[nc][2] * ea1 + tb1.x * eb1) * inv1,
                            (o[nc][3] * ea1 + tb1.y * eb1) * inv1);
        }
    }
}

extern "C" void kernel_launch(void* const* d_in, const int* in_sizes, int n_in,
                              void* d_out, int out_size)
{
    const float* q = (const float*)d_in[0];
    const float* k = (const float*)d_in[1];
    const float* v = (const float*)d_in[2];
    float*       o = (float*)d_out;

    cudaFuncSetAttribute(flash_attn_tf32_wg,
                         cudaFuncAttributeMaxDynamicSharedMemorySize,
                         (int)SMEM_BYTES);

    dim3 grid(SEQ / BM, BATCH);
    flash_attn_tf32_wg<<<grid, NTHR, SMEM_BYTES>>>(q, k, v, o);
}